// round 14
// baseline (speedup 1.0000x reference)
#include <cuda_runtime.h>

// HierarchicalPDFSampler — R13 structure + incremental-evaluation loop diet.
// 1 warp per ray.
//  - inverse-CDF by per-segment direct index ranges (u is linspace)
//  - start indices: bare ceil-guess via __float2int_ru (tiling repaired by
//    prefix-max)
//  - split indices: fast-div guess, clamped, uncorrected (R11-verified safe)
//  - two tight per-segment loops; sample value advanced incrementally
//    (s += slope*INV127), no u register in the loop
//  - closed-form merge ranks (no sort, no atomics, no tables)

constexpr int NC   = 64;
constexpr int NOUT = 192;
constexpr int WPB  = 8;
constexpr float INV127 = 1.0f / 127.0f;

// ~smallest j in [0,128] with j*INV127 >= c (uncorrected; repaired by prefix-max)
__device__ __forceinline__ int start_guess(float c) {
    int g = __float2int_ru(c * 127.0f);   // F2I.RU, saturating
    return max(0, min(g, 128));
}

// ~first j in [jS, jE] with fmaf(j*INV127, slope, offv) >= dn (clamped guess;
// any value in [jS,jE] yields a valid permutation — consumed consistently by
// both sample and depth placement)
__device__ __forceinline__ int split_guess(float slope, float offv, float dn,
                                           int jS, int jE) {
    const float uth = __fdividef(dn - offv, slope);   // inf/nan ok -> clamped
    int g = __float2int_ru(uth * 127.0f);
    return max(jS, min(g, jE));
}

__global__ __launch_bounds__(WPB * 32)
void hier_pdf_kernel(const float* __restrict__ depth,
                     const float* __restrict__ weights,
                     float* __restrict__ out,
                     int nrays)
{
    __shared__ float s_merg_all[WPB * NOUT];

    const int lane = threadIdx.x & 31;
    const int warp = threadIdx.x >> 5;
    const int ray  = blockIdx.x * WPB + warp;
    if (ray >= nrays) return;

    float* s_merg = s_merg_all + warp * NOUT;

    // ---- coalesced float2 loads ----
    const float2 d2 = ((const float2*)(depth   + (size_t)ray * NC))[lane];
    const float2 w2 = ((const float2*)(weights + (size_t)ray * NC))[lane];

    // ---- bin midpoints ----
    const float dnext  = __shfl_down_sync(0xffffffffu, d2.x, 1);  // depth[2l+2]
    const float b_even = 0.5f * (d2.x + d2.y);                    // bins[2l]
    const float b_odd  = 0.5f * (d2.y + dnext);                   // bins[2l+1]

    // ---- cdf via warp pair-scan of weights[1..62]+1e-5 ----
    const float a0 = (lane == 0)  ? 0.0f : (w2.x + 1e-5f);
    const float a1 = (lane == 31) ? 0.0f : (w2.y + 1e-5f);
    float incl = a0 + a1;
    #pragma unroll
    for (int off = 1; off < 32; off <<= 1) {
        const float t = __shfl_up_sync(0xffffffffu, incl, off);
        if (lane >= off) incl += t;
    }
    const float S      = __shfl_sync(0xffffffffu, incl, 31);
    const float invS   = __fdividef(1.0f, S);
    const float p_odd  = incl * invS;          // cdf[2l+1]
    const float p_even = (incl - a1) * invS;   // cdf[2l] (lane0: exactly 0)

    // ---- segment start indices + tiling repair (prefix-max) ----
    int jA = start_guess(p_even);   // start of segment b=2l
    int jB = start_guess(p_odd);    // start of segment b=2l+1
    jB = max(jB, jA);
    int v = jB;
    #pragma unroll
    for (int off = 1; off < 32; off <<= 1) {
        const int t = __shfl_up_sync(0xffffffffu, v, off);
        if (lane >= off) v = max(v, t);
    }
    int pm = __shfl_up_sync(0xffffffffu, v, 1);
    if (lane == 0) pm = 0;
    jA = max(jA, pm);
    jB = max(jB, jA);
    int jC = __shfl_down_sync(0xffffffffu, jA, 1);
    if (lane == 31) jC = 128;

    const float p_next = __shfl_down_sync(0xffffffffu, p_even, 1);  // cdf[2l+2]
    const float b_next = __shfl_down_sync(0xffffffffu, b_even, 1);  // bins[2l+2]

    // ---- segment coefficients ----
    // seg b=2l (lane31: b=62, 'above' clamps -> slope 0, range to 128)
    float ca1, ba1; int jE1;
    if (lane == 31) { ca1 = p_even; ba1 = b_even; jE1 = 128; }
    else            { ca1 = p_odd;  ba1 = b_odd;  jE1 = jB;  }
    const float den1   = ca1 - p_even;
    const float num1   = ba1 - b_even;
    const float slope1 = (den1 < 1e-5f) ? num1 : __fdividef(num1, den1);
    const float off1   = fmaf(-p_even, slope1, b_even);
    const int   sp1    = split_guess(slope1, off1, d2.y, jA, jE1);

    // seg b=2l+1 (lanes 0..30); lane31: sp2 = 128 (never triggers)
    float slope2 = 0.0f, off2 = 0.0f;
    int sp2 = jC;
    if (lane < 31) {
        const float den2 = p_next - p_odd;
        const float num2 = b_next - b_odd;
        slope2 = (den2 < 1e-5f) ? num2 : __fdividef(num2, den2);
        off2   = fmaf(-p_odd, slope2, b_odd);
        sp2    = split_guess(slope2, off2, dnext, jB, jC);
    }

    // ---- depth positions: e_i = jSplit(i-1), e_0 = 0 ----
    int e0 = __shfl_up_sync(0xffffffffu, sp2, 1);      // jSplit(2l-1)
    if (lane == 0) e0 = 0;
    s_merg[2 * lane     + e0]  = d2.x;
    s_merg[2 * lane + 1 + sp1] = d2.y;

    // ---- sample loops: seg1 then seg2, incremental value advance ----
    const int jEnd  = (lane == 31) ? 128 : jC;
    const int jBeff = (lane == 31) ? 128 : jB;   // lane31: loop2 gets 0 trips
    const int base  = 2 * lane + 1;

    int j = jA;
    {
        float s = fmaf((float)jA * INV127, slope1, off1);
        const float ds = slope1 * INV127;
        #pragma unroll 1
        for (; j < jBeff; ++j) {                 // segment b=2l
            const int pos = j + base + (j >= sp1 ? 1 : 0);
            s_merg[pos] = s;
            s += ds;
        }
    }
    if (j < jEnd) {
        float s = fmaf((float)j * INV127, slope2, off2);
        const float ds = slope2 * INV127;
        #pragma unroll 1
        for (; j < jEnd; ++j) {                  // segment b=2l+1
            const int pos = j + base + 1 + (j >= sp2 ? 1 : 0);
            s_merg[pos] = s;
            s += ds;
        }
    }
    __syncwarp();

    // ---- coalesced float4 store: 48 float4 per ray ----
    float4* orow = (float4*)(out + (size_t)ray * NOUT);
    const float4* m4 = (const float4*)s_merg;
    orow[lane] = m4[lane];
    if (lane < 16) orow[32 + lane] = m4[32 + lane];
}

extern "C" void kernel_launch(void* const* d_in, const int* in_sizes, int n_in,
                              void* d_out, int out_size)
{
    const float* depth   = (const float*)d_in[0];  // depth_rays_values_coarse [R,64]
    const float* weights = (const float*)d_in[1];  // coarse_weights           [R,64]
    float* out = (float*)d_out;                    // [R,192]

    const int nrays  = in_sizes[0] / NC;
    const int blocks = (nrays + WPB - 1) / WPB;
    hier_pdf_kernel<<<blocks, WPB * 32>>>(depth, weights, out, nrays);
}

// round 15
// speedup vs baseline: 1.1154x; 1.1154x over previous
#include <cuda_runtime.h>

// HierarchicalPDFSampler — 2 rays per warp (16 lanes per ray).
// All warp-collective setup (scan, prefix-max, shuffles) amortized over 2 rays
// via width-16 shuffle segments. Each lane owns 4 segments (unrolled).
// Same validated algorithm: direct inverse-CDF index ranges, clamped
// uncorrected guesses, closed-form merge ranks, no sort/atomics/tables.

constexpr int NC   = 64;
constexpr int NOUT = 192;
constexpr int RPB  = 16;   // rays per block (8 warps x 2)
constexpr float INV127 = 1.0f / 127.0f;

__device__ __forceinline__ int start_guess(float c) {
    int g = __float2int_ru(c * 127.0f);
    return max(0, min(g, 128));
}

// clamped fast guess of first j in [jS,jE] with fmaf(j*INV127,slope,offv)>=dn
__device__ __forceinline__ int split_guess(float slope, float offv, float dn,
                                           int jS, int jE) {
    const float uth = __fdividef(dn - offv, slope);   // inf/nan ok -> clamped
    int g = __float2int_ru(uth * 127.0f);
    return max(jS, min(g, jE));
}

__global__ __launch_bounds__(256)
void hier_pdf_kernel(const float* __restrict__ depth,
                     const float* __restrict__ weights,
                     float* __restrict__ out,
                     int nrays)
{
    __shared__ float s_merg_all[RPB * NOUT];   // 12 KB

    const unsigned FULL = 0xffffffffu;
    const int lane = threadIdx.x & 31;
    const int warp = threadIdx.x >> 5;
    const int t    = lane & 15;                 // lane within ray group
    const int slot = warp * 2 + (lane >> 4);    // ray slot in block [0,16)
    int ray = blockIdx.x * RPB + slot;
    if (ray >= nrays) ray = nrays - 1;          // duplicate work, same values

    float* s_merg = s_merg_all + slot * NOUT;

    // ---- coalesced float4 loads: elements 4t..4t+3 ----
    const float4 d4 = ((const float4*)(depth   + (size_t)ray * NC))[t];
    const float4 w4 = ((const float4*)(weights + (size_t)ray * NC))[t];

    // next lane's first depth element (depth[4t+4]); t=15: garbage, unused
    const float nx = __shfl_down_sync(FULL, d4.x, 1, 16);

    // ---- bin midpoints mids[4t..4t+3] ----
    const float m0 = 0.5f * (d4.x + d4.y);
    const float m1 = 0.5f * (d4.y + d4.z);
    const float m2 = 0.5f * (d4.z + d4.w);
    const float m3 = 0.5f * (d4.w + nx);

    // ---- masked weights a_k = w[k]+1e-5 (k=0,63 excluded) ----
    const float a0 = (t == 0)  ? 0.0f : (w4.x + 1e-5f);
    const float a1 = w4.y + 1e-5f;
    const float a2 = w4.z + 1e-5f;
    const float a3 = (t == 15) ? 0.0f : (w4.w + 1e-5f);

    // local prefixes + 16-lane Kogge-Stone scan of lane sums
    const float q0 = a0;
    const float q1 = q0 + a1;
    const float q2 = q1 + a2;
    const float ls = q2 + a3;
    float incl = ls;
    #pragma unroll
    for (int off = 1; off < 16; off <<= 1) {
        const float v = __shfl_up_sync(FULL, incl, off, 16);
        if (t >= off) incl += v;
    }
    const float S    = __shfl_sync(FULL, incl, 15, 16);
    const float invS = __fdividef(1.0f, S);
    const float excl = incl - ls;

    // cdf[4t..4t+3]; cdf[4t+4] from next lane
    const float c0 = (excl + q0) * invS;
    const float c1 = (excl + q1) * invS;
    const float c2 = (excl + q2) * invS;
    const float c3 = incl * invS;
    const float c4 = __shfl_down_sync(FULL, c0, 1, 16);
    const float m4 = __shfl_down_sync(FULL, m0, 1, 16);

    // ---- segment starts (local chain -> cross-lane prefix-max repair) ----
    int g0 = start_guess(c0);
    int g1 = max(start_guess(c1), g0);
    int g2 = max(start_guess(c2), g1);
    int g3 = max(start_guess(c3), g2);
    if (t == 15) g3 = 128;        // segment 63 doesn't exist; seg62 ends at 128

    int v = g3;
    #pragma unroll
    for (int off = 1; off < 16; off <<= 1) {
        const int tv = __shfl_up_sync(FULL, v, off, 16);
        if (t >= off) v = max(v, tv);
    }
    int pm = __shfl_up_sync(FULL, v, 1, 16);
    if (t == 0) pm = 0;
    g0 = max(g0, pm);
    g1 = max(g1, g0);
    g2 = max(g2, g1);
    g3 = max(g3, g2);
    int gN = __shfl_down_sync(FULL, g0, 1, 16);   // next lane's FINAL g0
    if (t == 15) gN = 128;

    // ---- per-segment coefficients + splits (fully unrolled, i=0..3) ----
    float lc[4] = {c0, c1, c2, c3};
    float hc[4] = {c1, c2, c3, c4};
    float lm[4] = {m0, m1, m2, m3};
    float hm[4] = {m1, m2, m3, m4};
    float dnv[4] = {d4.y, d4.z, d4.w, nx};
    int   gs[4] = {g0, g1, g2, g3};
    int   ge[4] = {g1, g2, g3, gN};
    if (t == 15) hm[2] = m2;   // seg 62: 'above' clamps -> slope 0, value m2

    float slope[4], offv[4];
    int sp[4];
    #pragma unroll
    for (int i = 0; i < 4; ++i) {
        const float den = hc[i] - lc[i];
        const float num = hm[i] - lm[i];
        const float sl  = (den < 1e-5f) ? num : __fdividef(num, den);
        slope[i] = sl;
        offv[i]  = fmaf(-lc[i], sl, lm[i]);
        sp[i]    = split_guess(sl, offv[i], dnv[i], gs[i], ge[i]);
    }

    // ---- depth positions: element k at k + sp[k-1] (k=0 -> +0) ----
    int spPrev = __shfl_up_sync(FULL, sp[3], 1, 16);
    if (t == 0) spPrev = 0;
    s_merg[4 * t + 0 + spPrev] = d4.x;
    s_merg[4 * t + 1 + sp[0]]  = d4.y;
    s_merg[4 * t + 2 + sp[1]]  = d4.z;
    s_merg[4 * t + 3 + sp[2]]  = d4.w;

    // ---- sample loops: 4 tight per-segment loops, fixed coefficients ----
    #pragma unroll
    for (int i = 0; i < 4; ++i) {
        const int bp1 = 4 * t + i + 1;
        const int spi = sp[i];
        const int jS  = gs[i], jE = ge[i];
        float s = fmaf((float)jS * INV127, slope[i], offv[i]);
        const float ds = slope[i] * INV127;
        #pragma unroll 1
        for (int j = jS; j < jE; ++j) {
            const int pos = j + bp1 + (j >= spi ? 1 : 0);
            s_merg[pos] = s;
            s += ds;
        }
    }
    __syncwarp();

    // ---- coalesced float4 store: 48 float4 per ray, 3 per lane ----
    float4* orow = (float4*)(out + (size_t)ray * NOUT);
    const float4* mv = (const float4*)s_merg;
    orow[t]      = mv[t];
    orow[t + 16] = mv[t + 16];
    orow[t + 32] = mv[t + 32];
}

extern "C" void kernel_launch(void* const* d_in, const int* in_sizes, int n_in,
                              void* d_out, int out_size)
{
    const float* depth   = (const float*)d_in[0];  // depth_rays_values_coarse [R,64]
    const float* weights = (const float*)d_in[1];  // coarse_weights           [R,64]
    float* out = (float*)d_out;                    // [R,192]

    const int nrays  = in_sizes[0] / NC;
    const int blocks = (nrays + RPB - 1) / RPB;
    hier_pdf_kernel<<<blocks, 256>>>(depth, weights, out, nrays);
}

// round 17
// speedup vs baseline: 1.1262x; 1.0097x over previous
#include <cuda_runtime.h>

// HierarchicalPDFSampler — 2 rays per warp (16 lanes per ray), occupancy push
// + trip-halved sample loops.
// All warp-collective setup amortized over 2 rays via width-16 shuffles.
// Each lane owns 4 segments (unrolled). Validated algorithm: direct
// inverse-CDF index ranges, clamped uncorrected guesses, closed-form merge
// ranks, no sort/atomics/tables.

constexpr int NC   = 64;
constexpr int NOUT = 192;
constexpr int RPB  = 16;   // rays per block (8 warps x 2)
constexpr float INV127 = 1.0f / 127.0f;

__device__ __forceinline__ int start_guess(float c) {
    int g = __float2int_ru(c * 127.0f);
    return max(0, min(g, 128));
}

__global__ __launch_bounds__(256, 7)
void hier_pdf_kernel(const float* __restrict__ depth,
                     const float* __restrict__ weights,
                     float* __restrict__ out,
                     int nrays)
{
    __shared__ float s_merg_all[RPB * NOUT];   // 12 KB

    const unsigned FULL = 0xffffffffu;
    const int lane = threadIdx.x & 31;
    const int warp = threadIdx.x >> 5;
    const int t    = lane & 15;                 // lane within ray group
    const int slot = warp * 2 + (lane >> 4);    // ray slot in block [0,16)
    int ray = blockIdx.x * RPB + slot;
    if (ray >= nrays) ray = nrays - 1;          // duplicate work, same values

    float* s_merg = s_merg_all + slot * NOUT;

    // ---- coalesced float4 loads: elements 4t..4t+3 ----
    const float4 d4 = ((const float4*)(depth   + (size_t)ray * NC))[t];
    const float4 w4 = ((const float4*)(weights + (size_t)ray * NC))[t];

    // next lane's first depth element (depth[4t+4]); t=15: garbage, unused
    const float nx = __shfl_down_sync(FULL, d4.x, 1, 16);

    // ---- bin midpoints mids[4t..4t+3] ----
    const float m0 = 0.5f * (d4.x + d4.y);
    const float m1 = 0.5f * (d4.y + d4.z);
    const float m2 = 0.5f * (d4.z + d4.w);
    const float m3 = 0.5f * (d4.w + nx);

    // ---- masked weights a_k = w[k]+1e-5 (k=0,63 excluded) ----
    const float a0 = (t == 0)  ? 0.0f : (w4.x + 1e-5f);
    const float a1 = w4.y + 1e-5f;
    const float a2 = w4.z + 1e-5f;
    const float a3 = (t == 15) ? 0.0f : (w4.w + 1e-5f);

    // local prefixes + 16-lane Kogge-Stone scan of lane sums
    const float q0 = a0;
    const float q1 = q0 + a1;
    const float q2 = q1 + a2;
    const float ls = q2 + a3;
    float incl = ls;
    #pragma unroll
    for (int off = 1; off < 16; off <<= 1) {
        const float v = __shfl_up_sync(FULL, incl, off, 16);
        if (t >= off) incl += v;
    }
    const float S    = __shfl_sync(FULL, incl, 15, 16);
    const float invS = __fdividef(1.0f, S);
    const float excl = incl - ls;

    // cdf[4t..4t+3]; cdf[4t+4] from next lane
    const float c0 = (excl + q0) * invS;
    const float c1 = (excl + q1) * invS;
    const float c2 = (excl + q2) * invS;
    const float c3 = incl * invS;
    const float c4 = __shfl_down_sync(FULL, c0, 1, 16);
    const float m4 = __shfl_down_sync(FULL, m0, 1, 16);

    // ---- segment starts (local chain -> cross-lane prefix-max repair) ----
    int g0 = start_guess(c0);
    int g1 = max(start_guess(c1), g0);
    int g2 = max(start_guess(c2), g1);
    int g3 = max(start_guess(c3), g2);
    if (t == 15) g3 = 128;        // segment 63 doesn't exist; seg62 ends at 128

    int v = g3;
    #pragma unroll
    for (int off = 1; off < 16; off <<= 1) {
        const int tv = __shfl_up_sync(FULL, v, off, 16);
        if (t >= off) v = max(v, tv);
    }
    int pm = __shfl_up_sync(FULL, v, 1, 16);
    if (t == 0) pm = 0;
    g0 = max(g0, pm);
    g1 = max(g1, g0);
    g2 = max(g2, g1);
    g3 = max(g3, g2);
    int gN = __shfl_down_sync(FULL, g0, 1, 16);   // next lane's FINAL g0
    if (t == 15) gN = 128;

    // ---- per-segment coefficients + splits (fully unrolled, i=0..3) ----
    float lc[4] = {c0, c1, c2, c3};
    float hc[4] = {c1, c2, c3, c4};
    float lm[4] = {m0, m1, m2, m3};
    float hm[4] = {m1, m2, m3, m4};
    float dnv[4] = {d4.y, d4.z, d4.w, nx};
    int   gs[4] = {g0, g1, g2, g3};
    int   ge[4] = {g1, g2, g3, gN};
    if (t == 15) hm[2] = m2;   // seg 62: 'above' clamps -> slope 0, value m2

    float slope[4], seed[4];
    int sp[4];
    #pragma unroll
    for (int i = 0; i < 4; ++i) {
        const float den = hc[i] - lc[i];
        const float num = hm[i] - lm[i];
        const float sl  = (den < 1e-5f) ? num : __fdividef(num, den);
        slope[i] = sl;
        // seed value at j = gs[i]:  s0 = (gs*INV127 - lc)*sl + lm
        seed[i]  = fmaf((float)gs[i] * INV127 - lc[i], sl, lm[i]);
        // split guess: first j with (j*INV127 - lc)*sl + lm >= dn
        const float uth = fmaf(__fdividef(dnv[i] - lm[i], sl), 1.0f, lc[i]);
        int g = __float2int_ru(uth * 127.0f);
        sp[i] = max(gs[i], min(g, ge[i]));
    }

    // ---- depth positions: element k at k + sp[k-1] (k=0 -> +0) ----
    int spPrev = __shfl_up_sync(FULL, sp[3], 1, 16);
    if (t == 0) spPrev = 0;
    s_merg[4 * t + 0 + spPrev] = d4.x;
    s_merg[4 * t + 1 + sp[0]]  = d4.y;
    s_merg[4 * t + 2 + sp[1]]  = d4.z;
    s_merg[4 * t + 3 + sp[2]]  = d4.w;

    // ---- sample loops: 4 per-segment loops, 2 samples per iteration ----
    #pragma unroll
    for (int i = 0; i < 4; ++i) {
        const int bp1 = 4 * t + i + 1;
        const int spi = sp[i];
        const int jE  = ge[i];
        int j = gs[i];
        float s = seed[i];
        const float ds  = slope[i] * INV127;
        // odd-length prologue
        if (((jE - j) & 1) && j < jE) {
            s_merg[j + bp1 + (j >= spi ? 1 : 0)] = s;
            s += ds; ++j;
        }
        const float ds2 = ds + ds;
        #pragma unroll 1
        for (; j < jE; j += 2) {
            const float s1 = s + ds;
            s_merg[j + bp1     + (j     >= spi ? 1 : 0)] = s;
            s_merg[j + 1 + bp1 + (j + 1 >= spi ? 1 : 0)] = s1;
            s += ds2;
        }
    }
    __syncwarp();

    // ---- coalesced float4 store: 48 float4 per ray, 3 per lane ----
    float4* orow = (float4*)(out + (size_t)ray * NOUT);
    const float4* mv = (const float4*)s_merg;
    orow[t]      = mv[t];
    orow[t + 16] = mv[t + 16];
    orow[t + 32] = mv[t + 32];
}

extern "C" void kernel_launch(void* const* d_in, const int* in_sizes, int n_in,
                              void* d_out, int out_size)
{
    const float* depth   = (const float*)d_in[0];  // depth_rays_values_coarse [R,64]
    const float* weights = (const float*)d_in[1];  // coarse_weights           [R,64]
    float* out = (float*)d_out;                    // [R,192]

    const int nrays  = in_sizes[0] / NC;
    const int blocks = (nrays + RPB - 1) / RPB;
    hier_pdf_kernel<<<blocks, 256>>>(depth, weights, out, nrays);
}